// round 13
// baseline (speedup 1.0000x reference)
#include <cuda_runtime.h>
#include <cuda_fp16.h>
#include <math.h>
#include <float.h>

#define NN 100000
#define EE 1600000
#define HH 64
#define CC 10
#define SCAN_BLK 1024
#define SCAN_NBLK ((NN + SCAN_BLK - 1) / SCAN_BLK)   // 98

// ---------------- static device scratch ----------------
__device__ int          g_dst[EE];
__device__ int          g_col[EE];
__device__ int          g_deg[NN];
__device__ int          g_rowptr[NN + 1];
__device__ int          g_cursor[NN];
__device__ int          g_blocksum[SCAN_NBLK];
__device__ unsigned int g_hh[NN * 32];       // fp16x2 node features (the only h)
__device__ unsigned int g_aggh[NN * 32];     // fp16x2 segment-max
__device__ int          g_odd_nonzero;

__device__ __forceinline__ uint4 hmax4(uint4 a, uint4 b) {
    uint4 r;
    *(__half2*)&r.x = __hmax2(*(__half2*)&a.x, *(__half2*)&b.x);
    *(__half2*)&r.y = __hmax2(*(__half2*)&a.y, *(__half2*)&b.y);
    *(__half2*)&r.z = __hmax2(*(__half2*)&a.z, *(__half2*)&b.z);
    *(__half2*)&r.w = __hmax2(*(__half2*)&a.w, *(__half2*)&b.w);
    return r;
}
__device__ __forceinline__ uint4 hadd4(uint4 a, uint4 b) {
    uint4 r;
    *(__half2*)&r.x = __hadd2(*(__half2*)&a.x, *(__half2*)&b.x);
    *(__half2*)&r.y = __hadd2(*(__half2*)&a.y, *(__half2*)&b.y);
    *(__half2*)&r.z = __hadd2(*(__half2*)&a.z, *(__half2*)&b.z);
    *(__half2*)&r.w = __hadd2(*(__half2*)&a.w, *(__half2*)&b.w);
    return r;
}

__device__ __forceinline__ void ldm_x4(unsigned& r0, unsigned& r1,
                                       unsigned& r2, unsigned& r3, unsigned addr) {
    asm volatile("ldmatrix.sync.aligned.m8n8.x4.shared.b16 {%0,%1,%2,%3}, [%4];"
                 : "=r"(r0), "=r"(r1), "=r"(r2), "=r"(r3) : "r"(addr));
}
__device__ __forceinline__ void ldm_x2t(unsigned& r0, unsigned& r1, unsigned addr) {
    asm volatile("ldmatrix.sync.aligned.m8n8.x2.trans.shared.b16 {%0,%1}, [%2];"
                 : "=r"(r0), "=r"(r1) : "r"(addr));
}
__device__ __forceinline__ void mma_f16(float c[4], unsigned a0, unsigned a1,
                                        unsigned a2, unsigned a3,
                                        unsigned b0, unsigned b1) {
    asm volatile("mma.sync.aligned.m16n8k16.row.col.f32.f16.f16.f32 "
                 "{%0,%1,%2,%3},{%4,%5,%6,%7},{%8,%9},{%0,%1,%2,%3};"
                 : "+f"(c[0]), "+f"(c[1]), "+f"(c[2]), "+f"(c[3])
                 : "r"(a0), "r"(a1), "r"(a2), "r"(a3), "r"(b0), "r"(b1));
}

// ---------------- setup: zero degrees + edge dtype detection ----------------
__global__ void zerodetect_kernel(const unsigned int* __restrict__ w) {
    int i = blockIdx.x * blockDim.x + threadIdx.x;
    if (i < NN) g_deg[i] = 0;
    if (i == 0) g_odd_nonzero = 0;
    if (i < 65536) {
        unsigned int v = w[2 * i + 1];
        if (v) atomicOr(&g_odd_nonzero, 1);
    }
}

__global__ void convert_kernel(const void* __restrict__ ei) {
    int i = blockIdx.x * blockDim.x + threadIdx.x;
    if (i >= EE) return;
    int d;
    if (g_odd_nonzero == 0) d = (int)((const long long*)ei)[EE + i];
    else                    d = ((const int*)ei)[EE + i];
    g_dst[i] = d;
    atomicAdd(&g_deg[d], 1);
}

// ---------------- multi-block exclusive scan (2 kernels) ----------------
__global__ void scan_phase1() {
    __shared__ int warp_sums[32];
    int tid = threadIdx.x;
    int i = blockIdx.x * SCAN_BLK + tid;
    int v = (i < NN) ? g_deg[i] : 0;
    int lane = tid & 31, wid = tid >> 5;
    int incl = v;
#pragma unroll
    for (int off = 1; off < 32; off <<= 1) {
        int t = __shfl_up_sync(0xffffffffu, incl, off);
        if (lane >= off) incl += t;
    }
    if (lane == 31) warp_sums[wid] = incl;
    __syncthreads();
    if (wid == 0) {
        int ws = warp_sums[lane];
        int wincl = ws;
#pragma unroll
        for (int off = 1; off < 32; off <<= 1) {
            int t = __shfl_up_sync(0xffffffffu, wincl, off);
            if (lane >= off) wincl += t;
        }
        warp_sums[lane] = wincl - ws;
        if (lane == 31) g_blocksum[blockIdx.x] = wincl;
    }
    __syncthreads();
    int excl = incl - v + warp_sums[wid];
    if (i < NN) g_rowptr[i] = excl;
}

// Phase 3 computes its own block offset inline (reduction over < bid sums).
__global__ void scan_phase3() {
    __shared__ int warp4[4];
    __shared__ int off_sh;
    int tid = threadIdx.x;
    int bid = blockIdx.x;
    if (tid < 128) {
        int lane = tid & 31, w = tid >> 5;
        int v = (tid < bid) ? g_blocksum[tid] : 0;   // bid <= 97 < 128
#pragma unroll
        for (int off = 16; off > 0; off >>= 1)
            v += __shfl_down_sync(0xffffffffu, v, off);
        if (lane == 0) warp4[w] = v;
    }
    __syncthreads();
    if (tid == 0) off_sh = warp4[0] + warp4[1] + warp4[2] + warp4[3];
    __syncthreads();
    int off = off_sh;
    int i = bid * SCAN_BLK + tid;
    if (i < NN) {
        int r = g_rowptr[i] + off;
        g_rowptr[i] = r;
        g_cursor[i] = r;
    }
    if (bid == SCAN_NBLK - 1 && tid == 0)
        g_rowptr[NN] = off + g_blocksum[SCAN_NBLK - 1];
}

__global__ void scatter_kernel(const void* __restrict__ ei) {
    int i = blockIdx.x * blockDim.x + threadIdx.x;
    if (i >= EE) return;
    int s;
    if (g_odd_nonzero == 0) s = (int)((const long long*)ei)[i];
    else                    s = ((const int*)ei)[i];
    int d = g_dst[i];
    int pos = atomicAdd(&g_cursor[d], 1);
    g_col[pos] = s;
}

// ---------------- segment max: 2 nodes per warp, 4 edges x 8 lanes each ----------------
// Two independent gather chains double per-warp outstanding loads (chip MLP is
// warp-occupancy-capped). Clamped indices keep the loop predicate-free; duplicate
// maxes are idempotent. __ldcg: L2-only (random 12.8MB working set never L1-hits).
__global__ void segmax_kernel() {
    int gw   = (blockIdx.x * blockDim.x + threadIdx.x) >> 5;
    int lane = threadIdx.x & 31;
    int n0 = gw * 2;
    if (n0 >= NN) return;
    int n1 = n0 + 1;                         // NN even -> always valid
    int grp = lane >> 3;
    int chunk = lane & 7;

    int beg0 = g_rowptr[n0], end0 = g_rowptr[n0 + 1];
    int beg1 = end0,         end1 = g_rowptr[n1 + 1];

    uint4 acc0, acc1;
    acc0.x = acc0.y = acc0.z = acc0.w = 0xFBFFFBFFu;   // (-65504,-65504)
    acc1 = acc0;

    int b0 = beg0, b1 = beg1;
    while (b0 < end0 || b1 < end1) {
        int cnt0 = min(32, end0 - b0);                 // may be <= 0
        int cnt1 = min(32, end1 - b1);
        int l0 = max(cnt0 - 1, 0), l1 = max(cnt1 - 1, 0);
        int s0 = g_col[min(b0 + min(lane, l0), EE - 1)];
        int s1 = g_col[min(b1 + min(lane, l1), EE - 1)];
        bool v0 = cnt0 > 0, v1 = cnt1 > 0;             // warp-uniform
        int em = max(cnt0, cnt1);
#pragma unroll 4
        for (int e4 = 0; e4 < em; e4 += 4) {
            int sv0 = __shfl_sync(0xffffffffu, s0, min(e4 + grp, l0));
            int sv1 = __shfl_sync(0xffffffffu, s1, min(e4 + grp, l1));
            if (v0) acc0 = hmax4(acc0, __ldcg((const uint4*)(g_hh + sv0 * 32 + chunk * 4)));
            if (v1) acc1 = hmax4(acc1, __ldcg((const uint4*)(g_hh + sv1 * 32 + chunk * 4)));
        }
        b0 += 32; b1 += 32;
    }

    // combine the 4 edge-groups
#pragma unroll
    for (int off = 8; off <= 16; off <<= 1) {
        uint4 o0, o1;
        o0.x = __shfl_xor_sync(0xffffffffu, acc0.x, off);
        o0.y = __shfl_xor_sync(0xffffffffu, acc0.y, off);
        o0.z = __shfl_xor_sync(0xffffffffu, acc0.z, off);
        o0.w = __shfl_xor_sync(0xffffffffu, acc0.w, off);
        acc0 = hmax4(acc0, o0);
        o1.x = __shfl_xor_sync(0xffffffffu, acc1.x, off);
        o1.y = __shfl_xor_sync(0xffffffffu, acc1.y, off);
        o1.z = __shfl_xor_sync(0xffffffffu, acc1.z, off);
        o1.w = __shfl_xor_sync(0xffffffffu, acc1.w, off);
        acc1 = hmax4(acc1, o1);
    }

    if (beg0 == end0) { acc0.x = acc0.y = acc0.z = acc0.w = 0u; }
    if (beg1 == end1) { acc1.x = acc1.y = acc1.z = acc1.w = 0u; }

    if (grp == 0) {
        ((uint4*)g_aggh)[n0 * 8 + chunk] = acc0;
        ((uint4*)g_aggh)[n1 * 8 + chunk] = acc1;
    }
}

// ---------------- fp16 tensor-core GEMM: hh_out = (A) @ W + b ----------------
template <bool ENC>
__global__ void __launch_bounds__(256)
gemm_h16_kernel(const float* __restrict__ Ax,
                const unsigned* __restrict__ Hh,
                const unsigned* __restrict__ Aggh,
                const float* __restrict__ W,
                const float* __restrict__ bias,
                unsigned* __restrict__ OutHh, int n) {
    __shared__ __align__(16) __half As[64 * 72];
    __shared__ __align__(16) __half WsH[64 * 72];
    __shared__ __align__(16) __half WsL[64 * 72];

    int tid = threadIdx.x;
    int block_row = blockIdx.x * 64;

    for (int i = tid; i < 1024; i += 256) {
        int k = i >> 4, c4 = i & 15;
        float4 v = ((const float4*)W)[i];
        __half h0 = __float2half_rn(v.x), h1 = __float2half_rn(v.y);
        __half h2 = __float2half_rn(v.z), h3 = __float2half_rn(v.w);
        __half l0 = __float2half_rn(v.x - __half2float(h0));
        __half l1 = __float2half_rn(v.y - __half2float(h1));
        __half l2 = __float2half_rn(v.z - __half2float(h2));
        __half l3 = __float2half_rn(v.w - __half2float(h3));
        __half* ph = &WsH[k * 72 + c4 * 4];
        ph[0] = h0; ph[1] = h1; ph[2] = h2; ph[3] = h3;
        __half* pl = &WsL[k * 72 + c4 * 4];
        pl[0] = l0; pl[1] = l1; pl[2] = l2; pl[3] = l3;
    }

    if (ENC) {
        for (int i = tid; i < 1024; i += 256) {
            int m = i >> 4, c = i & 15;
            int row = block_row + m;
            float4 v = make_float4(0.f, 0.f, 0.f, 0.f);
            if (row < n) v = ((const float4*)Ax)[row * 16 + c];
            __half* p = &As[m * 72 + c * 4];
            p[0] = __float2half_rn(v.x); p[1] = __float2half_rn(v.y);
            p[2] = __float2half_rn(v.z); p[3] = __float2half_rn(v.w);
        }
    } else {
        for (int i = tid; i < 512; i += 256) {
            int m = i >> 3, c4 = i & 7;
            int row = block_row + m;
            uint4 v = make_uint4(0u, 0u, 0u, 0u);
            if (row < n) {
                uint4 hv = ((const uint4*)Hh)[row * 8 + c4];
                uint4 av = ((const uint4*)Aggh)[row * 8 + c4];
                v = hadd4(hv, av);
            }
            *(uint4*)&As[m * 72 + c4 * 8] = v;
        }
    }
    __syncthreads();

    int lane = tid & 31, wid = tid >> 5;
    int m0 = (wid & 3) * 16;
    int n0 = (wid >> 2) * 32;

    unsigned sAs = (unsigned)__cvta_generic_to_shared(As);
    unsigned sWH = (unsigned)__cvta_generic_to_shared(WsH);
    unsigned sWL = (unsigned)__cvta_generic_to_shared(WsL);

    int a_row = m0 + ((lane >> 3) & 1) * 8 + (lane & 7);
    int a_k   = ((lane >> 4) & 1) * 8;
    unsigned a_addr = sAs + (a_row * 72 + a_k) * 2;
    int b_k = lane & 15;

    float c[4][4];
#pragma unroll
    for (int i = 0; i < 4; i++)
#pragma unroll
        for (int j = 0; j < 4; j++) c[i][j] = 0.f;

#pragma unroll
    for (int ks = 0; ks < 4; ks++) {
        unsigned a0, a1, a2, a3;
        ldm_x4(a0, a1, a2, a3, a_addr + ks * 32);
        unsigned brow = ((ks * 16 + b_k) * 72 + n0) * 2;
#pragma unroll
        for (int nt = 0; nt < 4; nt++) {
            unsigned bh0, bh1, bl0, bl1;
            ldm_x2t(bh0, bh1, sWH + brow + nt * 16);
            ldm_x2t(bl0, bl1, sWL + brow + nt * 16);
            mma_f16(c[nt], a0, a1, a2, a3, bh0, bh1);
            mma_f16(c[nt], a0, a1, a2, a3, bl0, bl1);
        }
    }

    int g2 = lane >> 2, t = lane & 3;
#pragma unroll
    for (int nt = 0; nt < 4; nt++) {
        int col = n0 + nt * 8 + 2 * t;
        float2 bb = *(const float2*)&bias[col];
        int r0 = block_row + m0 + g2;
        int r1 = r0 + 8;
        if (r0 < n) {
            __half2 p = __floats2half2_rn(c[nt][0] + bb.x, c[nt][1] + bb.y);
            OutHh[r0 * 32 + (col >> 1)] = *(unsigned*)&p;
        }
        if (r1 < n) {
            __half2 p = __floats2half2_rn(c[nt][2] + bb.x, c[nt][3] + bb.y);
            OutHh[r1 * 32 + (col >> 1)] = *(unsigned*)&p;
        }
    }
}

// ---------------- decoder + log-softmax (fp16 h input) ----------------
__global__ void decoder_kernel(const unsigned* __restrict__ Hh,
                               const float* __restrict__ dw,
                               const float* __restrict__ db,
                               float* __restrict__ out, int n) {
    __shared__ float Ws[HH * CC];
    __shared__ float bs[CC];
    int tid = threadIdx.x;
    for (int i = tid; i < HH * CC; i += blockDim.x) Ws[i] = dw[i];
    if (tid < CC) bs[tid] = db[tid];
    __syncthreads();
    int node = blockIdx.x * blockDim.x + tid;
    if (node >= n) return;
    float acc[CC];
#pragma unroll
    for (int c = 0; c < CC; c++) acc[c] = bs[c];
    const unsigned* hp = Hh + node * 32;
#pragma unroll
    for (int k2 = 0; k2 < 32; k2++) {
        unsigned pv = hp[k2];
        float2 v = __half22float2(*(__half2*)&pv);
        int kb = k2 * 2;
#pragma unroll
        for (int c = 0; c < CC; c++)
            acc[c] += v.x * Ws[(kb + 0) * CC + c] + v.y * Ws[(kb + 1) * CC + c];
    }
    float mx = acc[0];
#pragma unroll
    for (int c = 1; c < CC; c++) mx = fmaxf(mx, acc[c]);
    float s = 0.f;
#pragma unroll
    for (int c = 0; c < CC; c++) s += expf(acc[c] - mx);
    float lse = mx + logf(s);
#pragma unroll
    for (int c = 0; c < CC; c++) out[node * CC + c] = acc[c] - lse;
}

// ---------------- launch ----------------
extern "C" void kernel_launch(void* const* d_in, const int* in_sizes, int n_in,
                              void* d_out, int out_size) {
    const float* x      = (const float*)d_in[0];
    const void*  ei     = d_in[1];
    const float* enc_w  = (const float*)d_in[3];
    const float* enc_b  = (const float*)d_in[4];
    const float* proc_w = (const float*)d_in[5];
    const float* proc_b = (const float*)d_in[6];
    const float* dec_w  = (const float*)d_in[7];
    const float* dec_b  = (const float*)d_in[8];
    float* out = (float*)d_out;

    unsigned* hhptr = nullptr;
    unsigned* agghptr = nullptr;
    cudaGetSymbolAddress((void**)&hhptr, g_hh);
    cudaGetSymbolAddress((void**)&agghptr, g_aggh);

    const int n = NN;
    const int ggrid = (n + 63) / 64;

    // fork: encoder GEMM runs concurrently with CSR build
    cudaStream_t s2;
    cudaStreamCreateWithFlags(&s2, cudaStreamNonBlocking);
    cudaEvent_t e0, e1;
    cudaEventCreateWithFlags(&e0, cudaEventDisableTiming);
    cudaEventCreateWithFlags(&e1, cudaEventDisableTiming);
    cudaEventRecord(e0, 0);
    cudaStreamWaitEvent(s2, e0, 0);

    // encoder on s2 (fp32 x -> fp16 h)
    gemm_h16_kernel<true><<<ggrid, 256, 0, s2>>>(x, nullptr, nullptr,
                                                 enc_w, enc_b, hhptr, n);
    cudaEventRecord(e1, s2);

    // CSR build on capture stream
    zerodetect_kernel<<<(NN + 255) / 256, 256>>>((const unsigned int*)ei);
    convert_kernel<<<(EE + 255) / 256, 256>>>(ei);
    scan_phase1<<<SCAN_NBLK, SCAN_BLK>>>();
    scan_phase3<<<SCAN_NBLK, SCAN_BLK>>>();
    scatter_kernel<<<(EE + 255) / 256, 256>>>(ei);

    // join
    cudaStreamWaitEvent(0, e1, 0);

    // 6 GIN layers (segmax: 2 nodes per warp)
    for (int it = 0; it < 6; it++) {
        segmax_kernel<<<((NN / 2) * 32 + 255) / 256, 256>>>();
        gemm_h16_kernel<false><<<ggrid, 256>>>(nullptr, hhptr, agghptr,
                                               proc_w, proc_b, hhptr, n);
    }

    // decoder + log-softmax
    decoder_kernel<<<(n + 127) / 128, 128>>>(hhptr, dec_w, dec_b, out, n);
}

// round 14
// speedup vs baseline: 1.0437x; 1.0437x over previous
#include <cuda_runtime.h>
#include <cuda_fp16.h>
#include <math.h>
#include <float.h>

#define NN 100000
#define EE 1600000
#define HH 64
#define CC 10
#define SCAN_BLK 1024
#define SCAN_NBLK ((NN + SCAN_BLK - 1) / SCAN_BLK)   // 98

// ---------------- static device scratch ----------------
__device__ int          g_dst[EE];
__device__ int          g_col[EE];
__device__ int          g_deg[NN];
__device__ int          g_rowptr[NN + 1];
__device__ int          g_cursor[NN];
__device__ int          g_blocksum[SCAN_NBLK];
__device__ unsigned int g_hh[NN * 32];       // fp16x2 node features (the only h)
__device__ unsigned int g_aggh[NN * 32];     // fp16x2 segment-max
__device__ int          g_odd_nonzero;

__device__ __forceinline__ uint4 hmax4(uint4 a, uint4 b) {
    uint4 r;
    *(__half2*)&r.x = __hmax2(*(__half2*)&a.x, *(__half2*)&b.x);
    *(__half2*)&r.y = __hmax2(*(__half2*)&a.y, *(__half2*)&b.y);
    *(__half2*)&r.z = __hmax2(*(__half2*)&a.z, *(__half2*)&b.z);
    *(__half2*)&r.w = __hmax2(*(__half2*)&a.w, *(__half2*)&b.w);
    return r;
}
__device__ __forceinline__ uint4 hadd4(uint4 a, uint4 b) {
    uint4 r;
    *(__half2*)&r.x = __hadd2(*(__half2*)&a.x, *(__half2*)&b.x);
    *(__half2*)&r.y = __hadd2(*(__half2*)&a.y, *(__half2*)&b.y);
    *(__half2*)&r.z = __hadd2(*(__half2*)&a.z, *(__half2*)&b.z);
    *(__half2*)&r.w = __hadd2(*(__half2*)&a.w, *(__half2*)&b.w);
    return r;
}

__device__ __forceinline__ void ldm_x4(unsigned& r0, unsigned& r1,
                                       unsigned& r2, unsigned& r3, unsigned addr) {
    asm volatile("ldmatrix.sync.aligned.m8n8.x4.shared.b16 {%0,%1,%2,%3}, [%4];"
                 : "=r"(r0), "=r"(r1), "=r"(r2), "=r"(r3) : "r"(addr));
}
__device__ __forceinline__ void ldm_x2t(unsigned& r0, unsigned& r1, unsigned addr) {
    asm volatile("ldmatrix.sync.aligned.m8n8.x2.trans.shared.b16 {%0,%1}, [%2];"
                 : "=r"(r0), "=r"(r1) : "r"(addr));
}
__device__ __forceinline__ void mma_f16(float c[4], unsigned a0, unsigned a1,
                                        unsigned a2, unsigned a3,
                                        unsigned b0, unsigned b1) {
    asm volatile("mma.sync.aligned.m16n8k16.row.col.f32.f16.f16.f32 "
                 "{%0,%1,%2,%3},{%4,%5,%6,%7},{%8,%9},{%0,%1,%2,%3};"
                 : "+f"(c[0]), "+f"(c[1]), "+f"(c[2]), "+f"(c[3])
                 : "r"(a0), "r"(a1), "r"(a2), "r"(a3), "r"(b0), "r"(b1));
}

// ---------------- setup: zero degrees + edge dtype detection ----------------
__global__ void zerodetect_kernel(const unsigned int* __restrict__ w) {
    int i = blockIdx.x * blockDim.x + threadIdx.x;
    if (i < NN) g_deg[i] = 0;
    if (i == 0) g_odd_nonzero = 0;
    if (i < 65536) {
        unsigned int v = w[2 * i + 1];
        if (v) atomicOr(&g_odd_nonzero, 1);
    }
}

__global__ void convert_kernel(const void* __restrict__ ei) {
    int i = blockIdx.x * blockDim.x + threadIdx.x;
    if (i >= EE) return;
    int d;
    if (g_odd_nonzero == 0) d = (int)((const long long*)ei)[EE + i];
    else                    d = ((const int*)ei)[EE + i];
    g_dst[i] = d;
    atomicAdd(&g_deg[d], 1);
}

// ---------------- multi-block exclusive scan (2 kernels) ----------------
__global__ void scan_phase1() {
    __shared__ int warp_sums[32];
    int tid = threadIdx.x;
    int i = blockIdx.x * SCAN_BLK + tid;
    int v = (i < NN) ? g_deg[i] : 0;
    int lane = tid & 31, wid = tid >> 5;
    int incl = v;
#pragma unroll
    for (int off = 1; off < 32; off <<= 1) {
        int t = __shfl_up_sync(0xffffffffu, incl, off);
        if (lane >= off) incl += t;
    }
    if (lane == 31) warp_sums[wid] = incl;
    __syncthreads();
    if (wid == 0) {
        int ws = warp_sums[lane];
        int wincl = ws;
#pragma unroll
        for (int off = 1; off < 32; off <<= 1) {
            int t = __shfl_up_sync(0xffffffffu, wincl, off);
            if (lane >= off) wincl += t;
        }
        warp_sums[lane] = wincl - ws;
        if (lane == 31) g_blocksum[blockIdx.x] = wincl;
    }
    __syncthreads();
    int excl = incl - v + warp_sums[wid];
    if (i < NN) g_rowptr[i] = excl;
}

// Phase 3 computes its own block offset inline (reduction over < bid sums).
__global__ void scan_phase3() {
    __shared__ int warp4[4];
    __shared__ int off_sh;
    int tid = threadIdx.x;
    int bid = blockIdx.x;
    if (tid < 128) {
        int lane = tid & 31, w = tid >> 5;
        int v = (tid < bid) ? g_blocksum[tid] : 0;   // bid <= 97 < 128
#pragma unroll
        for (int off = 16; off > 0; off >>= 1)
            v += __shfl_down_sync(0xffffffffu, v, off);
        if (lane == 0) warp4[w] = v;
    }
    __syncthreads();
    if (tid == 0) off_sh = warp4[0] + warp4[1] + warp4[2] + warp4[3];
    __syncthreads();
    int off = off_sh;
    int i = bid * SCAN_BLK + tid;
    if (i < NN) {
        int r = g_rowptr[i] + off;
        g_rowptr[i] = r;
        g_cursor[i] = r;
    }
    if (bid == SCAN_NBLK - 1 && tid == 0)
        g_rowptr[NN] = off + g_blocksum[SCAN_NBLK - 1];
}

__global__ void scatter_kernel(const void* __restrict__ ei) {
    int i = blockIdx.x * blockDim.x + threadIdx.x;
    if (i >= EE) return;
    int s;
    if (g_odd_nonzero == 0) s = (int)((const long long*)ei)[i];
    else                    s = ((const int*)ei)[i];
    int d = g_dst[i];
    int pos = atomicAdd(&g_cursor[d], 1);
    g_col[pos] = s;
}

// ---------------- segment max: 1 warp per node, 4 edges x 8 lanes ----------------
// Predicate-free inner loop via index clamping (duplicate maxes idempotent);
// unroll 4 -> 4 independent LDG.128 per lane in flight.  (R12-proven version.)
__global__ void segmax_kernel() {
    int gw   = (blockIdx.x * blockDim.x + threadIdx.x) >> 5;
    int lane = threadIdx.x & 31;
    if (gw >= NN) return;
    int beg = g_rowptr[gw], end = g_rowptr[gw + 1];
    int grp = lane >> 3;
    int chunk = lane & 7;

    uint4 acc;
    acc.x = acc.y = acc.z = acc.w = 0xFBFFFBFFu;   // (-65504, -65504) half2

    for (int base = beg; base < end; base += 32) {
        int cnt = min(32, end - base);
        int s = g_col[base + min(lane, cnt - 1)];
#pragma unroll 4
        for (int e4 = 0; e4 < cnt; e4 += 4) {
            int sl = min(e4 + grp, cnt - 1);
            int sv = __shfl_sync(0xffffffffu, s, sl);
            uint4 v = *(const uint4*)(g_hh + sv * 32 + chunk * 4);
            acc = hmax4(acc, v);
        }
    }
#pragma unroll
    for (int off = 8; off <= 16; off <<= 1) {
        uint4 o;
        o.x = __shfl_xor_sync(0xffffffffu, acc.x, off);
        o.y = __shfl_xor_sync(0xffffffffu, acc.y, off);
        o.z = __shfl_xor_sync(0xffffffffu, acc.z, off);
        o.w = __shfl_xor_sync(0xffffffffu, acc.w, off);
        acc = hmax4(acc, o);
    }
    if (beg == end) { acc.x = acc.y = acc.z = acc.w = 0u; }
    if (grp == 0)
        ((uint4*)g_aggh)[gw * 8 + chunk] = acc;
}

// ---------------- fp16 tensor-core GEMM: hh_out = (A) @ W + b ----------------
template <bool ENC>
__global__ void __launch_bounds__(256)
gemm_h16_kernel(const float* __restrict__ Ax,
                const unsigned* __restrict__ Hh,
                const unsigned* __restrict__ Aggh,
                const float* __restrict__ W,
                const float* __restrict__ bias,
                unsigned* __restrict__ OutHh, int n) {
    __shared__ __align__(16) __half As[64 * 72];
    __shared__ __align__(16) __half WsH[64 * 72];
    __shared__ __align__(16) __half WsL[64 * 72];

    int tid = threadIdx.x;
    int block_row = blockIdx.x * 64;

    for (int i = tid; i < 1024; i += 256) {
        int k = i >> 4, c4 = i & 15;
        float4 v = ((const float4*)W)[i];
        __half h0 = __float2half_rn(v.x), h1 = __float2half_rn(v.y);
        __half h2 = __float2half_rn(v.z), h3 = __float2half_rn(v.w);
        __half l0 = __float2half_rn(v.x - __half2float(h0));
        __half l1 = __float2half_rn(v.y - __half2float(h1));
        __half l2 = __float2half_rn(v.z - __half2float(h2));
        __half l3 = __float2half_rn(v.w - __half2float(h3));
        __half* ph = &WsH[k * 72 + c4 * 4];
        ph[0] = h0; ph[1] = h1; ph[2] = h2; ph[3] = h3;
        __half* pl = &WsL[k * 72 + c4 * 4];
        pl[0] = l0; pl[1] = l1; pl[2] = l2; pl[3] = l3;
    }

    if (ENC) {
        for (int i = tid; i < 1024; i += 256) {
            int m = i >> 4, c = i & 15;
            int row = block_row + m;
            float4 v = make_float4(0.f, 0.f, 0.f, 0.f);
            if (row < n) v = ((const float4*)Ax)[row * 16 + c];
            __half* p = &As[m * 72 + c * 4];
            p[0] = __float2half_rn(v.x); p[1] = __float2half_rn(v.y);
            p[2] = __float2half_rn(v.z); p[3] = __float2half_rn(v.w);
        }
    } else {
        for (int i = tid; i < 512; i += 256) {
            int m = i >> 3, c4 = i & 7;
            int row = block_row + m;
            uint4 v = make_uint4(0u, 0u, 0u, 0u);
            if (row < n) {
                uint4 hv = ((const uint4*)Hh)[row * 8 + c4];
                uint4 av = ((const uint4*)Aggh)[row * 8 + c4];
                v = hadd4(hv, av);
            }
            *(uint4*)&As[m * 72 + c4 * 8] = v;
        }
    }
    __syncthreads();

    int lane = tid & 31, wid = tid >> 5;
    int m0 = (wid & 3) * 16;
    int n0 = (wid >> 2) * 32;

    unsigned sAs = (unsigned)__cvta_generic_to_shared(As);
    unsigned sWH = (unsigned)__cvta_generic_to_shared(WsH);
    unsigned sWL = (unsigned)__cvta_generic_to_shared(WsL);

    int a_row = m0 + ((lane >> 3) & 1) * 8 + (lane & 7);
    int a_k   = ((lane >> 4) & 1) * 8;
    unsigned a_addr = sAs + (a_row * 72 + a_k) * 2;
    int b_k = lane & 15;

    float c[4][4];
#pragma unroll
    for (int i = 0; i < 4; i++)
#pragma unroll
        for (int j = 0; j < 4; j++) c[i][j] = 0.f;

#pragma unroll
    for (int ks = 0; ks < 4; ks++) {
        unsigned a0, a1, a2, a3;
        ldm_x4(a0, a1, a2, a3, a_addr + ks * 32);
        unsigned brow = ((ks * 16 + b_k) * 72 + n0) * 2;
#pragma unroll
        for (int nt = 0; nt < 4; nt++) {
            unsigned bh0, bh1, bl0, bl1;
            ldm_x2t(bh0, bh1, sWH + brow + nt * 16);
            ldm_x2t(bl0, bl1, sWL + brow + nt * 16);
            mma_f16(c[nt], a0, a1, a2, a3, bh0, bh1);
            mma_f16(c[nt], a0, a1, a2, a3, bl0, bl1);
        }
    }

    int g2 = lane >> 2, t = lane & 3;
#pragma unroll
    for (int nt = 0; nt < 4; nt++) {
        int col = n0 + nt * 8 + 2 * t;
        float2 bb = *(const float2*)&bias[col];
        int r0 = block_row + m0 + g2;
        int r1 = r0 + 8;
        if (r0 < n) {
            __half2 p = __floats2half2_rn(c[nt][0] + bb.x, c[nt][1] + bb.y);
            OutHh[r0 * 32 + (col >> 1)] = *(unsigned*)&p;
        }
        if (r1 < n) {
            __half2 p = __floats2half2_rn(c[nt][2] + bb.x, c[nt][3] + bb.y);
            OutHh[r1 * 32 + (col >> 1)] = *(unsigned*)&p;
        }
    }
}

// ---------------- decoder + log-softmax (fp16 h input) ----------------
__global__ void decoder_kernel(const unsigned* __restrict__ Hh,
                               const float* __restrict__ dw,
                               const float* __restrict__ db,
                               float* __restrict__ out, int n) {
    __shared__ float Ws[HH * CC];
    __shared__ float bs[CC];
    int tid = threadIdx.x;
    for (int i = tid; i < HH * CC; i += blockDim.x) Ws[i] = dw[i];
    if (tid < CC) bs[tid] = db[tid];
    __syncthreads();
    int node = blockIdx.x * blockDim.x + tid;
    if (node >= n) return;
    float acc[CC];
#pragma unroll
    for (int c = 0; c < CC; c++) acc[c] = bs[c];
    const unsigned* hp = Hh + node * 32;
#pragma unroll
    for (int k2 = 0; k2 < 32; k2++) {
        unsigned pv = hp[k2];
        float2 v = __half22float2(*(__half2*)&pv);
        int kb = k2 * 2;
#pragma unroll
        for (int c = 0; c < CC; c++)
            acc[c] += v.x * Ws[(kb + 0) * CC + c] + v.y * Ws[(kb + 1) * CC + c];
    }
    float mx = acc[0];
#pragma unroll
    for (int c = 1; c < CC; c++) mx = fmaxf(mx, acc[c]);
    float s = 0.f;
#pragma unroll
    for (int c = 0; c < CC; c++) s += expf(acc[c] - mx);
    float lse = mx + logf(s);
#pragma unroll
    for (int c = 0; c < CC; c++) out[node * CC + c] = acc[c] - lse;
}

// ---------------- launch ----------------
extern "C" void kernel_launch(void* const* d_in, const int* in_sizes, int n_in,
                              void* d_out, int out_size) {
    const float* x      = (const float*)d_in[0];
    const void*  ei     = d_in[1];
    const float* enc_w  = (const float*)d_in[3];
    const float* enc_b  = (const float*)d_in[4];
    const float* proc_w = (const float*)d_in[5];
    const float* proc_b = (const float*)d_in[6];
    const float* dec_w  = (const float*)d_in[7];
    const float* dec_b  = (const float*)d_in[8];
    float* out = (float*)d_out;

    unsigned* hhptr = nullptr;
    unsigned* agghptr = nullptr;
    cudaGetSymbolAddress((void**)&hhptr, g_hh);
    cudaGetSymbolAddress((void**)&agghptr, g_aggh);

    const int n = NN;
    const int ggrid = (n + 63) / 64;

    // fork: encoder GEMM runs concurrently with CSR build
    cudaStream_t s2;
    cudaStreamCreateWithFlags(&s2, cudaStreamNonBlocking);
    cudaEvent_t e0, e1;
    cudaEventCreateWithFlags(&e0, cudaEventDisableTiming);
    cudaEventCreateWithFlags(&e1, cudaEventDisableTiming);
    cudaEventRecord(e0, 0);
    cudaStreamWaitEvent(s2, e0, 0);

    // encoder on s2 (fp32 x -> fp16 h)
    gemm_h16_kernel<true><<<ggrid, 256, 0, s2>>>(x, nullptr, nullptr,
                                                 enc_w, enc_b, hhptr, n);
    cudaEventRecord(e1, s2);

    // CSR build on capture stream
    zerodetect_kernel<<<(NN + 255) / 256, 256>>>((const unsigned int*)ei);
    convert_kernel<<<(EE + 255) / 256, 256>>>(ei);
    scan_phase1<<<SCAN_NBLK, SCAN_BLK>>>();
    scan_phase3<<<SCAN_NBLK, SCAN_BLK>>>();
    scatter_kernel<<<(EE + 255) / 256, 256>>>(ei);

    // join
    cudaStreamWaitEvent(0, e1, 0);

    // 6 GIN layers
    for (int it = 0; it < 6; it++) {
        segmax_kernel<<<(NN * 32 + 255) / 256, 256>>>();
        gemm_h16_kernel<false><<<ggrid, 256>>>(nullptr, hhptr, agghptr,
                                               proc_w, proc_b, hhptr, n);
    }

    // decoder + log-softmax
    decoder_kernel<<<(n + 127) / 128, 128>>>(hhptr, dec_w, dec_b, out, n);
}

// round 15
// speedup vs baseline: 1.0962x; 1.0502x over previous
#include <cuda_runtime.h>
#include <cuda_fp16.h>
#include <math.h>
#include <float.h>

#define NN 100000
#define EE 1600000
#define HH 64
#define CC 10
#define SCAN_BLK 1024
#define SCAN_NBLK ((NN + SCAN_BLK - 1) / SCAN_BLK)   // 98

// ---------------- static device scratch ----------------
__device__ int          g_dst[EE];
__device__ int          g_col[EE];
__device__ int          g_deg[NN];
__device__ int          g_rowptr[NN + 1];
__device__ int          g_cursor[NN];
__device__ int          g_blocksum[SCAN_NBLK];
__device__ unsigned int g_hh[NN * 32];       // fp16x2 node features (the only h)
__device__ unsigned int g_aggh[NN * 32];     // fp16x2 segment-max
__device__ int          g_odd_nonzero;

__device__ __forceinline__ uint4 hmax4(uint4 a, uint4 b) {
    uint4 r;
    *(__half2*)&r.x = __hmax2(*(__half2*)&a.x, *(__half2*)&b.x);
    *(__half2*)&r.y = __hmax2(*(__half2*)&a.y, *(__half2*)&b.y);
    *(__half2*)&r.z = __hmax2(*(__half2*)&a.z, *(__half2*)&b.z);
    *(__half2*)&r.w = __hmax2(*(__half2*)&a.w, *(__half2*)&b.w);
    return r;
}
__device__ __forceinline__ uint4 hadd4(uint4 a, uint4 b) {
    uint4 r;
    *(__half2*)&r.x = __hadd2(*(__half2*)&a.x, *(__half2*)&b.x);
    *(__half2*)&r.y = __hadd2(*(__half2*)&a.y, *(__half2*)&b.y);
    *(__half2*)&r.z = __hadd2(*(__half2*)&a.z, *(__half2*)&b.z);
    *(__half2*)&r.w = __hadd2(*(__half2*)&a.w, *(__half2*)&b.w);
    return r;
}

__device__ __forceinline__ void ldm_x4(unsigned& r0, unsigned& r1,
                                       unsigned& r2, unsigned& r3, unsigned addr) {
    asm volatile("ldmatrix.sync.aligned.m8n8.x4.shared.b16 {%0,%1,%2,%3}, [%4];"
                 : "=r"(r0), "=r"(r1), "=r"(r2), "=r"(r3) : "r"(addr));
}
__device__ __forceinline__ void ldm_x2t(unsigned& r0, unsigned& r1, unsigned addr) {
    asm volatile("ldmatrix.sync.aligned.m8n8.x2.trans.shared.b16 {%0,%1}, [%2];"
                 : "=r"(r0), "=r"(r1) : "r"(addr));
}
__device__ __forceinline__ void mma_f16(float c[4], unsigned a0, unsigned a1,
                                        unsigned a2, unsigned a3,
                                        unsigned b0, unsigned b1) {
    asm volatile("mma.sync.aligned.m16n8k16.row.col.f32.f16.f16.f32 "
                 "{%0,%1,%2,%3},{%4,%5,%6,%7},{%8,%9},{%0,%1,%2,%3};"
                 : "+f"(c[0]), "+f"(c[1]), "+f"(c[2]), "+f"(c[3])
                 : "r"(a0), "r"(a1), "r"(a2), "r"(a3), "r"(b0), "r"(b1));
}

// ---------------- setup: zero degrees + edge dtype detection ----------------
__global__ void zerodetect_kernel(const unsigned int* __restrict__ w) {
    int i = blockIdx.x * blockDim.x + threadIdx.x;
    if (i < NN) g_deg[i] = 0;
    if (i == 0) g_odd_nonzero = 0;
    if (i < 65536) {
        unsigned int v = w[2 * i + 1];
        if (v) atomicOr(&g_odd_nonzero, 1);
    }
}

__global__ void convert_kernel(const void* __restrict__ ei) {
    int i = blockIdx.x * blockDim.x + threadIdx.x;
    if (i >= EE) return;
    int d;
    if (g_odd_nonzero == 0) d = (int)((const long long*)ei)[EE + i];
    else                    d = ((const int*)ei)[EE + i];
    g_dst[i] = d;
    atomicAdd(&g_deg[d], 1);
}

// ---------------- multi-block exclusive scan (2 kernels) ----------------
__global__ void scan_phase1() {
    __shared__ int warp_sums[32];
    int tid = threadIdx.x;
    int i = blockIdx.x * SCAN_BLK + tid;
    int v = (i < NN) ? g_deg[i] : 0;
    int lane = tid & 31, wid = tid >> 5;
    int incl = v;
#pragma unroll
    for (int off = 1; off < 32; off <<= 1) {
        int t = __shfl_up_sync(0xffffffffu, incl, off);
        if (lane >= off) incl += t;
    }
    if (lane == 31) warp_sums[wid] = incl;
    __syncthreads();
    if (wid == 0) {
        int ws = warp_sums[lane];
        int wincl = ws;
#pragma unroll
        for (int off = 1; off < 32; off <<= 1) {
            int t = __shfl_up_sync(0xffffffffu, wincl, off);
            if (lane >= off) wincl += t;
        }
        warp_sums[lane] = wincl - ws;
        if (lane == 31) g_blocksum[blockIdx.x] = wincl;
    }
    __syncthreads();
    int excl = incl - v + warp_sums[wid];
    if (i < NN) g_rowptr[i] = excl;
}

// Phase 3 computes its own block offset inline (reduction over < bid sums).
__global__ void scan_phase3() {
    __shared__ int warp4[4];
    __shared__ int off_sh;
    int tid = threadIdx.x;
    int bid = blockIdx.x;
    if (tid < 128) {
        int lane = tid & 31, w = tid >> 5;
        int v = (tid < bid) ? g_blocksum[tid] : 0;   // bid <= 97 < 128
#pragma unroll
        for (int off = 16; off > 0; off >>= 1)
            v += __shfl_down_sync(0xffffffffu, v, off);
        if (lane == 0) warp4[w] = v;
    }
    __syncthreads();
    if (tid == 0) off_sh = warp4[0] + warp4[1] + warp4[2] + warp4[3];
    __syncthreads();
    int off = off_sh;
    int i = bid * SCAN_BLK + tid;
    if (i < NN) {
        int r = g_rowptr[i] + off;
        g_rowptr[i] = r;
        g_cursor[i] = r;
    }
    if (bid == SCAN_NBLK - 1 && tid == 0)
        g_rowptr[NN] = off + g_blocksum[SCAN_NBLK - 1];
}

__global__ void scatter_kernel(const void* __restrict__ ei) {
    int i = blockIdx.x * blockDim.x + threadIdx.x;
    if (i >= EE) return;
    int s;
    if (g_odd_nonzero == 0) s = (int)((const long long*)ei)[i];
    else                    s = ((const int*)ei)[i];
    int d = g_dst[i];
    int pos = atomicAdd(&g_cursor[d], 1);
    g_col[pos] = s;
}

// ---------------- segment max: 1 warp per node, 4 edges x 8 lanes ----------------
__global__ void segmax_kernel() {
    int gw   = (blockIdx.x * blockDim.x + threadIdx.x) >> 5;
    int lane = threadIdx.x & 31;
    if (gw >= NN) return;
    int beg = g_rowptr[gw], end = g_rowptr[gw + 1];
    int grp = lane >> 3;
    int chunk = lane & 7;

    uint4 acc;
    acc.x = acc.y = acc.z = acc.w = 0xFBFFFBFFu;   // (-65504, -65504) half2

    for (int base = beg; base < end; base += 32) {
        int cnt = min(32, end - base);
        int s = g_col[base + min(lane, cnt - 1)];
#pragma unroll 4
        for (int e4 = 0; e4 < cnt; e4 += 4) {
            int sl = min(e4 + grp, cnt - 1);
            int sv = __shfl_sync(0xffffffffu, s, sl);
            uint4 v = *(const uint4*)(g_hh + sv * 32 + chunk * 4);
            acc = hmax4(acc, v);
        }
    }
#pragma unroll
    for (int off = 8; off <= 16; off <<= 1) {
        uint4 o;
        o.x = __shfl_xor_sync(0xffffffffu, acc.x, off);
        o.y = __shfl_xor_sync(0xffffffffu, acc.y, off);
        o.z = __shfl_xor_sync(0xffffffffu, acc.z, off);
        o.w = __shfl_xor_sync(0xffffffffu, acc.w, off);
        acc = hmax4(acc, o);
    }
    if (beg == end) { acc.x = acc.y = acc.z = acc.w = 0u; }
    if (grp == 0)
        ((uint4*)g_aggh)[gw * 8 + chunk] = acc;
}

// ---------------- fp16 tensor-core GEMM (+fused decoder in DEC mode) ----------------
// MODE 0 (ENC): A = fp32 x -> fp16; store hh.
// MODE 1 (MID): A = hh + aggh;     store hh.
// MODE 2 (DEC): A = hh + aggh; keep fp32 result in smem, run decoder +
//               log-softmax in-block, write out directly. No hh store.
template <int MODE>
__global__ void __launch_bounds__(256)
gemm_h16_kernel(const float* __restrict__ Ax,
                const unsigned* __restrict__ Hh,
                const unsigned* __restrict__ Aggh,
                const float* __restrict__ W,
                const float* __restrict__ bias,
                unsigned* __restrict__ OutHh,
                const float* __restrict__ dw,
                const float* __restrict__ db,
                float* __restrict__ out, int n) {
    __shared__ __align__(16) __half As[64 * 72];
    __shared__ __align__(16) __half WsH[64 * 72];
    __shared__ __align__(16) __half WsL[64 * 72];
    __shared__ float Hs[(MODE == 2) ? 64 * 66 : 1];
    __shared__ float DWs[(MODE == 2) ? (HH * CC + CC) : 1];

    int tid = threadIdx.x;
    int block_row = blockIdx.x * 64;

    for (int i = tid; i < 1024; i += 256) {
        int k = i >> 4, c4 = i & 15;
        float4 v = ((const float4*)W)[i];
        __half h0 = __float2half_rn(v.x), h1 = __float2half_rn(v.y);
        __half h2 = __float2half_rn(v.z), h3 = __float2half_rn(v.w);
        __half l0 = __float2half_rn(v.x - __half2float(h0));
        __half l1 = __float2half_rn(v.y - __half2float(h1));
        __half l2 = __float2half_rn(v.z - __half2float(h2));
        __half l3 = __float2half_rn(v.w - __half2float(h3));
        __half* ph = &WsH[k * 72 + c4 * 4];
        ph[0] = h0; ph[1] = h1; ph[2] = h2; ph[3] = h3;
        __half* pl = &WsL[k * 72 + c4 * 4];
        pl[0] = l0; pl[1] = l1; pl[2] = l2; pl[3] = l3;
    }

    if (MODE == 2) {
        for (int i = tid; i < HH * CC; i += 256) DWs[i] = dw[i];
        if (tid < CC) DWs[HH * CC + tid] = db[tid];
    }

    if (MODE == 0) {
        for (int i = tid; i < 1024; i += 256) {
            int m = i >> 4, c = i & 15;
            int row = block_row + m;
            float4 v = make_float4(0.f, 0.f, 0.f, 0.f);
            if (row < n) v = ((const float4*)Ax)[row * 16 + c];
            __half* p = &As[m * 72 + c * 4];
            p[0] = __float2half_rn(v.x); p[1] = __float2half_rn(v.y);
            p[2] = __float2half_rn(v.z); p[3] = __float2half_rn(v.w);
        }
    } else {
        for (int i = tid; i < 512; i += 256) {
            int m = i >> 3, c4 = i & 7;
            int row = block_row + m;
            uint4 v = make_uint4(0u, 0u, 0u, 0u);
            if (row < n) {
                uint4 hv = ((const uint4*)Hh)[row * 8 + c4];
                uint4 av = ((const uint4*)Aggh)[row * 8 + c4];
                v = hadd4(hv, av);
            }
            *(uint4*)&As[m * 72 + c4 * 8] = v;
        }
    }
    __syncthreads();

    int lane = tid & 31, wid = tid >> 5;
    int m0 = (wid & 3) * 16;
    int n0 = (wid >> 2) * 32;

    unsigned sAs = (unsigned)__cvta_generic_to_shared(As);
    unsigned sWH = (unsigned)__cvta_generic_to_shared(WsH);
    unsigned sWL = (unsigned)__cvta_generic_to_shared(WsL);

    int a_row = m0 + ((lane >> 3) & 1) * 8 + (lane & 7);
    int a_k   = ((lane >> 4) & 1) * 8;
    unsigned a_addr = sAs + (a_row * 72 + a_k) * 2;
    int b_k = lane & 15;

    float c[4][4];
#pragma unroll
    for (int i = 0; i < 4; i++)
#pragma unroll
        for (int j = 0; j < 4; j++) c[i][j] = 0.f;

#pragma unroll
    for (int ks = 0; ks < 4; ks++) {
        unsigned a0, a1, a2, a3;
        ldm_x4(a0, a1, a2, a3, a_addr + ks * 32);
        unsigned brow = ((ks * 16 + b_k) * 72 + n0) * 2;
#pragma unroll
        for (int nt = 0; nt < 4; nt++) {
            unsigned bh0, bh1, bl0, bl1;
            ldm_x2t(bh0, bh1, sWH + brow + nt * 16);
            ldm_x2t(bl0, bl1, sWL + brow + nt * 16);
            mma_f16(c[nt], a0, a1, a2, a3, bh0, bh1);
            mma_f16(c[nt], a0, a1, a2, a3, bl0, bl1);
        }
    }

    int g2 = lane >> 2, t = lane & 3;
    if (MODE == 2) {
        // stage fp32 h to smem
#pragma unroll
        for (int nt = 0; nt < 4; nt++) {
            int col = n0 + nt * 8 + 2 * t;
            float2 bb = *(const float2*)&bias[col];
            int r0 = m0 + g2;
            Hs[r0 * 66 + col]           = c[nt][0] + bb.x;
            Hs[r0 * 66 + col + 1]       = c[nt][1] + bb.y;
            Hs[(r0 + 8) * 66 + col]     = c[nt][2] + bb.x;
            Hs[(r0 + 8) * 66 + col + 1] = c[nt][3] + bb.y;
        }
        __syncthreads();
        // decoder + log-softmax: thread tid<64 owns one row
        if (tid < 64) {
            int row = block_row + tid;
            if (row < n) {
                float acc[CC];
#pragma unroll
                for (int cc = 0; cc < CC; cc++) acc[cc] = DWs[HH * CC + cc];
#pragma unroll 8
                for (int k = 0; k < HH; k++) {
                    float hv = Hs[tid * 66 + k];
#pragma unroll
                    for (int cc = 0; cc < CC; cc++)
                        acc[cc] += hv * DWs[k * CC + cc];
                }
                float mx = acc[0];
#pragma unroll
                for (int cc = 1; cc < CC; cc++) mx = fmaxf(mx, acc[cc]);
                float s = 0.f;
#pragma unroll
                for (int cc = 0; cc < CC; cc++) s += expf(acc[cc] - mx);
                float lse = mx + logf(s);
#pragma unroll
                for (int cc = 0; cc < CC; cc++) out[row * CC + cc] = acc[cc] - lse;
            }
        }
    } else {
#pragma unroll
        for (int nt = 0; nt < 4; nt++) {
            int col = n0 + nt * 8 + 2 * t;
            float2 bb = *(const float2*)&bias[col];
            int r0 = block_row + m0 + g2;
            int r1 = r0 + 8;
            if (r0 < n) {
                __half2 p = __floats2half2_rn(c[nt][0] + bb.x, c[nt][1] + bb.y);
                OutHh[r0 * 32 + (col >> 1)] = *(unsigned*)&p;
            }
            if (r1 < n) {
                __half2 p = __floats2half2_rn(c[nt][2] + bb.x, c[nt][3] + bb.y);
                OutHh[r1 * 32 + (col >> 1)] = *(unsigned*)&p;
            }
        }
    }
}

// ---------------- launch ----------------
extern "C" void kernel_launch(void* const* d_in, const int* in_sizes, int n_in,
                              void* d_out, int out_size) {
    const float* x      = (const float*)d_in[0];
    const void*  ei     = d_in[1];
    const float* enc_w  = (const float*)d_in[3];
    const float* enc_b  = (const float*)d_in[4];
    const float* proc_w = (const float*)d_in[5];
    const float* proc_b = (const float*)d_in[6];
    const float* dec_w  = (const float*)d_in[7];
    const float* dec_b  = (const float*)d_in[8];
    float* out = (float*)d_out;

    unsigned* hhptr = nullptr;
    unsigned* agghptr = nullptr;
    cudaGetSymbolAddress((void**)&hhptr, g_hh);
    cudaGetSymbolAddress((void**)&agghptr, g_aggh);

    const int n = NN;
    const int ggrid = (n + 63) / 64;

    // fork: encoder GEMM runs concurrently with CSR build
    cudaStream_t s2;
    cudaStreamCreateWithFlags(&s2, cudaStreamNonBlocking);
    cudaEvent_t e0, e1;
    cudaEventCreateWithFlags(&e0, cudaEventDisableTiming);
    cudaEventCreateWithFlags(&e1, cudaEventDisableTiming);
    cudaEventRecord(e0, 0);
    cudaStreamWaitEvent(s2, e0, 0);

    // encoder on s2 (fp32 x -> fp16 h)
    gemm_h16_kernel<0><<<ggrid, 256, 0, s2>>>(x, nullptr, nullptr, enc_w, enc_b,
                                              hhptr, nullptr, nullptr, nullptr, n);
    cudaEventRecord(e1, s2);

    // CSR build on capture stream
    zerodetect_kernel<<<(NN + 255) / 256, 256>>>((const unsigned int*)ei);
    convert_kernel<<<(EE + 255) / 256, 256>>>(ei);
    scan_phase1<<<SCAN_NBLK, SCAN_BLK>>>();
    scan_phase3<<<SCAN_NBLK, SCAN_BLK>>>();
    scatter_kernel<<<(EE + 255) / 256, 256>>>(ei);

    // join
    cudaStreamWaitEvent(0, e1, 0);

    // 5 GIN layers (MID)
    for (int it = 0; it < 5; it++) {
        segmax_kernel<<<(NN * 32 + 255) / 256, 256>>>();
        gemm_h16_kernel<1><<<ggrid, 256>>>(nullptr, hhptr, agghptr, proc_w, proc_b,
                                           hhptr, nullptr, nullptr, nullptr, n);
    }
    // 6th layer fused with decoder + log-softmax (DEC)
    segmax_kernel<<<(NN * 32 + 255) / 256, 256>>>();
    gemm_h16_kernel<2><<<ggrid, 256>>>(nullptr, hhptr, agghptr, proc_w, proc_b,
                                       hhptr, dec_w, dec_b, out, n);
}

// round 16
// speedup vs baseline: 1.1336x; 1.0342x over previous
#include <cuda_runtime.h>
#include <cuda_fp16.h>
#include <math.h>
#include <float.h>

#define NN 100000
#define EE 1600000
#define HH 64
#define CC 10
#define SCAN_BLK 1024
#define SCAN_NBLK ((NN + SCAN_BLK - 1) / SCAN_BLK)   // 98

// ---------------- static device scratch ----------------
__device__ int          g_dst[EE];
__device__ int          g_col[EE];
__device__ int          g_deg[NN];
__device__ int          g_rowptr[NN + 1];
__device__ int          g_cursor[NN];
__device__ int          g_blocksum[SCAN_NBLK];
__device__ unsigned int g_hh[NN * 32];       // fp16x2 node features (the only h)
__device__ unsigned int g_aggh[NN * 32];     // fp16x2 segment-max
__device__ int          g_odd_nonzero;

// PDL: no-ops if the kernel wasn't launched with programmatic serialization.
__device__ __forceinline__ void gdc_launch() {
    asm volatile("griddepcontrol.launch_dependents;" ::: "memory");
}
__device__ __forceinline__ void gdc_wait() {
    asm volatile("griddepcontrol.wait;" ::: "memory");
}

__device__ __forceinline__ uint4 hmax4(uint4 a, uint4 b) {
    uint4 r;
    *(__half2*)&r.x = __hmax2(*(__half2*)&a.x, *(__half2*)&b.x);
    *(__half2*)&r.y = __hmax2(*(__half2*)&a.y, *(__half2*)&b.y);
    *(__half2*)&r.z = __hmax2(*(__half2*)&a.z, *(__half2*)&b.z);
    *(__half2*)&r.w = __hmax2(*(__half2*)&a.w, *(__half2*)&b.w);
    return r;
}
__device__ __forceinline__ uint4 hadd4(uint4 a, uint4 b) {
    uint4 r;
    *(__half2*)&r.x = __hadd2(*(__half2*)&a.x, *(__half2*)&b.x);
    *(__half2*)&r.y = __hadd2(*(__half2*)&a.y, *(__half2*)&b.y);
    *(__half2*)&r.z = __hadd2(*(__half2*)&a.z, *(__half2*)&b.z);
    *(__half2*)&r.w = __hadd2(*(__half2*)&a.w, *(__half2*)&b.w);
    return r;
}

__device__ __forceinline__ void ldm_x4(unsigned& r0, unsigned& r1,
                                       unsigned& r2, unsigned& r3, unsigned addr) {
    asm volatile("ldmatrix.sync.aligned.m8n8.x4.shared.b16 {%0,%1,%2,%3}, [%4];"
                 : "=r"(r0), "=r"(r1), "=r"(r2), "=r"(r3) : "r"(addr));
}
__device__ __forceinline__ void ldm_x2t(unsigned& r0, unsigned& r1, unsigned addr) {
    asm volatile("ldmatrix.sync.aligned.m8n8.x2.trans.shared.b16 {%0,%1}, [%2];"
                 : "=r"(r0), "=r"(r1) : "r"(addr));
}
__device__ __forceinline__ void mma_f16(float c[4], unsigned a0, unsigned a1,
                                        unsigned a2, unsigned a3,
                                        unsigned b0, unsigned b1) {
    asm volatile("mma.sync.aligned.m16n8k16.row.col.f32.f16.f16.f32 "
                 "{%0,%1,%2,%3},{%4,%5,%6,%7},{%8,%9},{%0,%1,%2,%3};"
                 : "+f"(c[0]), "+f"(c[1]), "+f"(c[2]), "+f"(c[3])
                 : "r"(a0), "r"(a1), "r"(a2), "r"(a3), "r"(b0), "r"(b1));
}

// ---------------- setup: zero degrees + edge dtype detection ----------------
__global__ void zerodetect_kernel(const unsigned int* __restrict__ w) {
    gdc_launch();
    int i = blockIdx.x * blockDim.x + threadIdx.x;
    if (i < NN) g_deg[i] = 0;
    if (i == 0) g_odd_nonzero = 0;
    if (i < 65536) {
        unsigned int v = w[2 * i + 1];
        if (v) atomicOr(&g_odd_nonzero, 1);
    }
}

__global__ void convert_kernel(const void* __restrict__ ei) {
    gdc_launch();
    int i = blockIdx.x * blockDim.x + threadIdx.x;
    if (i >= EE) return;
    gdc_wait();                 // flag + deg zeroing from zerodetect
    int d;
    if (g_odd_nonzero == 0) d = (int)((const long long*)ei)[EE + i];
    else                    d = ((const int*)ei)[EE + i];
    g_dst[i] = d;
    atomicAdd(&g_deg[d], 1);
}

// ---------------- multi-block exclusive scan (2 kernels) ----------------
__global__ void scan_phase1() {
    gdc_launch();
    __shared__ int warp_sums[32];
    int tid = threadIdx.x;
    int i = blockIdx.x * SCAN_BLK + tid;
    gdc_wait();                 // deg from convert
    int v = (i < NN) ? g_deg[i] : 0;
    int lane = tid & 31, wid = tid >> 5;
    int incl = v;
#pragma unroll
    for (int off = 1; off < 32; off <<= 1) {
        int t = __shfl_up_sync(0xffffffffu, incl, off);
        if (lane >= off) incl += t;
    }
    if (lane == 31) warp_sums[wid] = incl;
    __syncthreads();
    if (wid == 0) {
        int ws = warp_sums[lane];
        int wincl = ws;
#pragma unroll
        for (int off = 1; off < 32; off <<= 1) {
            int t = __shfl_up_sync(0xffffffffu, wincl, off);
            if (lane >= off) wincl += t;
        }
        warp_sums[lane] = wincl - ws;
        if (lane == 31) g_blocksum[blockIdx.x] = wincl;
    }
    __syncthreads();
    int excl = incl - v + warp_sums[wid];
    if (i < NN) g_rowptr[i] = excl;
}

// Phase 3 computes its own block offset inline (reduction over < bid sums).
__global__ void scan_phase3() {
    gdc_launch();
    __shared__ int warp4[4];
    __shared__ int off_sh;
    int tid = threadIdx.x;
    int bid = blockIdx.x;
    gdc_wait();                 // blocksum + rowptr from phase1
    if (tid < 128) {
        int lane = tid & 31, w = tid >> 5;
        int v = (tid < bid) ? g_blocksum[tid] : 0;   // bid <= 97 < 128
#pragma unroll
        for (int off = 16; off > 0; off >>= 1)
            v += __shfl_down_sync(0xffffffffu, v, off);
        if (lane == 0) warp4[w] = v;
    }
    __syncthreads();
    if (tid == 0) off_sh = warp4[0] + warp4[1] + warp4[2] + warp4[3];
    __syncthreads();
    int off = off_sh;
    int i = bid * SCAN_BLK + tid;
    if (i < NN) {
        int r = g_rowptr[i] + off;
        g_rowptr[i] = r;
        g_cursor[i] = r;
    }
    if (bid == SCAN_NBLK - 1 && tid == 0)
        g_rowptr[NN] = off + g_blocksum[SCAN_NBLK - 1];
}

__global__ void scatter_kernel(const void* __restrict__ ei) {
    gdc_launch();
    int i = blockIdx.x * blockDim.x + threadIdx.x;
    if (i >= EE) return;
    // pre-wait: edge data + dst (convert/zerodetect transitively complete
    // before this kernel's prelaunch window opens)
    int s;
    if (g_odd_nonzero == 0) s = (int)((const long long*)ei)[i];
    else                    s = ((const int*)ei)[i];
    int d = g_dst[i];
    gdc_wait();                 // cursor from scan_phase3
    int pos = atomicAdd(&g_cursor[d], 1);
    g_col[pos] = s;
}

// ---------------- segment max: 1 warp per node, 4 edges x 8 lanes ----------------
__global__ void segmax_kernel() {
    gdc_launch();
    int gw   = (blockIdx.x * blockDim.x + threadIdx.x) >> 5;
    int lane = threadIdx.x & 31;
    if (gw >= NN) return;
    int beg = g_rowptr[gw], end = g_rowptr[gw + 1];   // pre-wait: rowptr stable
    int grp = lane >> 3;
    int chunk = lane & 7;

    uint4 acc;
    acc.x = acc.y = acc.z = acc.w = 0xFBFFFBFFu;   // (-65504, -65504) half2

    gdc_wait();   // col (first layer: scatter) + hh (later: previous GEMM)

    for (int base = beg; base < end; base += 32) {
        int cnt = min(32, end - base);
        int s = g_col[base + min(lane, cnt - 1)];
#pragma unroll 4
        for (int e4 = 0; e4 < cnt; e4 += 4) {
            int sl = min(e4 + grp, cnt - 1);
            int sv = __shfl_sync(0xffffffffu, s, sl);
            uint4 v = *(const uint4*)(g_hh + sv * 32 + chunk * 4);
            acc = hmax4(acc, v);
        }
    }
#pragma unroll
    for (int off = 8; off <= 16; off <<= 1) {
        uint4 o;
        o.x = __shfl_xor_sync(0xffffffffu, acc.x, off);
        o.y = __shfl_xor_sync(0xffffffffu, acc.y, off);
        o.z = __shfl_xor_sync(0xffffffffu, acc.z, off);
        o.w = __shfl_xor_sync(0xffffffffu, acc.w, off);
        acc = hmax4(acc, o);
    }
    if (beg == end) { acc.x = acc.y = acc.z = acc.w = 0u; }
    if (grp == 0)
        ((uint4*)g_aggh)[gw * 8 + chunk] = acc;
}

// ---------------- fp16 tensor-core GEMM (+fused decoder in DEC mode) ----------------
// MODE 0 (ENC): A = fp32 x -> fp16; store hh.
// MODE 1 (MID): A = hh + aggh;     store hh.
// MODE 2 (DEC): A = hh + aggh; fp32 result to smem, decoder + log-softmax
//               in-block, write out directly.
template <int MODE>
__global__ void __launch_bounds__(256)
gemm_h16_kernel(const float* __restrict__ Ax,
                const unsigned* __restrict__ Hh,
                const unsigned* __restrict__ Aggh,
                const float* __restrict__ W,
                const float* __restrict__ bias,
                unsigned* __restrict__ OutHh,
                const float* __restrict__ dw,
                const float* __restrict__ db,
                float* __restrict__ out, int n) {
    __shared__ __align__(16) __half As[64 * 72];
    __shared__ __align__(16) __half WsH[64 * 72];
    __shared__ __align__(16) __half WsL[64 * 72];
    __shared__ float Hs[(MODE == 2) ? 64 * 66 : 1];
    __shared__ float DWs[(MODE == 2) ? (HH * CC + CC) : 1];

    gdc_launch();
    int tid = threadIdx.x;
    int block_row = blockIdx.x * 64;

    // pre-wait prologue: W/bias/decoder weights are input constants
    for (int i = tid; i < 1024; i += 256) {
        int k = i >> 4, c4 = i & 15;
        float4 v = ((const float4*)W)[i];
        __half h0 = __float2half_rn(v.x), h1 = __float2half_rn(v.y);
        __half h2 = __float2half_rn(v.z), h3 = __float2half_rn(v.w);
        __half l0 = __float2half_rn(v.x - __half2float(h0));
        __half l1 = __float2half_rn(v.y - __half2float(h1));
        __half l2 = __float2half_rn(v.z - __half2float(h2));
        __half l3 = __float2half_rn(v.w - __half2float(h3));
        __half* ph = &WsH[k * 72 + c4 * 4];
        ph[0] = h0; ph[1] = h1; ph[2] = h2; ph[3] = h3;
        __half* pl = &WsL[k * 72 + c4 * 4];
        pl[0] = l0; pl[1] = l1; pl[2] = l2; pl[3] = l3;
    }
    if (MODE == 2) {
        for (int i = tid; i < HH * CC; i += 256) DWs[i] = dw[i];
        if (tid < CC) DWs[HH * CC + tid] = db[tid];
    }

    gdc_wait();   // hh / aggh from previous kernels

    if (MODE == 0) {
        for (int i = tid; i < 1024; i += 256) {
            int m = i >> 4, c = i & 15;
            int row = block_row + m;
            float4 v = make_float4(0.f, 0.f, 0.f, 0.f);
            if (row < n) v = ((const float4*)Ax)[row * 16 + c];
            __half* p = &As[m * 72 + c * 4];
            p[0] = __float2half_rn(v.x); p[1] = __float2half_rn(v.y);
            p[2] = __float2half_rn(v.z); p[3] = __float2half_rn(v.w);
        }
    } else {
        for (int i = tid; i < 512; i += 256) {
            int m = i >> 3, c4 = i & 7;
            int row = block_row + m;
            uint4 v = make_uint4(0u, 0u, 0u, 0u);
            if (row < n) {
                uint4 hv = ((const uint4*)Hh)[row * 8 + c4];
                uint4 av = ((const uint4*)Aggh)[row * 8 + c4];
                v = hadd4(hv, av);
            }
            *(uint4*)&As[m * 72 + c4 * 8] = v;
        }
    }
    __syncthreads();

    int lane = tid & 31, wid = tid >> 5;
    int m0 = (wid & 3) * 16;
    int n0 = (wid >> 2) * 32;

    unsigned sAs = (unsigned)__cvta_generic_to_shared(As);
    unsigned sWH = (unsigned)__cvta_generic_to_shared(WsH);
    unsigned sWL = (unsigned)__cvta_generic_to_shared(WsL);

    int a_row = m0 + ((lane >> 3) & 1) * 8 + (lane & 7);
    int a_k   = ((lane >> 4) & 1) * 8;
    unsigned a_addr = sAs + (a_row * 72 + a_k) * 2;
    int b_k = lane & 15;

    float c[4][4];
#pragma unroll
    for (int i = 0; i < 4; i++)
#pragma unroll
        for (int j = 0; j < 4; j++) c[i][j] = 0.f;

#pragma unroll
    for (int ks = 0; ks < 4; ks++) {
        unsigned a0, a1, a2, a3;
        ldm_x4(a0, a1, a2, a3, a_addr + ks * 32);
        unsigned brow = ((ks * 16 + b_k) * 72 + n0) * 2;
#pragma unroll
        for (int nt = 0; nt < 4; nt++) {
            unsigned bh0, bh1, bl0, bl1;
            ldm_x2t(bh0, bh1, sWH + brow + nt * 16);
            ldm_x2t(bl0, bl1, sWL + brow + nt * 16);
            mma_f16(c[nt], a0, a1, a2, a3, bh0, bh1);
            mma_f16(c[nt], a0, a1, a2, a3, bl0, bl1);
        }
    }

    int g2 = lane >> 2, t = lane & 3;
    if (MODE == 2) {
#pragma unroll
        for (int nt = 0; nt < 4; nt++) {
            int col = n0 + nt * 8 + 2 * t;
            float2 bb = *(const float2*)&bias[col];
            int r0 = m0 + g2;
            Hs[r0 * 66 + col]           = c[nt][0] + bb.x;
            Hs[r0 * 66 + col + 1]       = c[nt][1] + bb.y;
            Hs[(r0 + 8) * 66 + col]     = c[nt][2] + bb.x;
            Hs[(r0 + 8) * 66 + col + 1] = c[nt][3] + bb.y;
        }
        __syncthreads();
        if (tid < 64) {
            int row = block_row + tid;
            if (row < n) {
                float acc[CC];
#pragma unroll
                for (int cc = 0; cc < CC; cc++) acc[cc] = DWs[HH * CC + cc];
#pragma unroll 8
                for (int k = 0; k < HH; k++) {
                    float hv = Hs[tid * 66 + k];
#pragma unroll
                    for (int cc = 0; cc < CC; cc++)
                        acc[cc] += hv * DWs[k * CC + cc];
                }
                float mx = acc[0];
#pragma unroll
                for (int cc = 1; cc < CC; cc++) mx = fmaxf(mx, acc[cc]);
                float s = 0.f;
#pragma unroll
                for (int cc = 0; cc < CC; cc++) s += expf(acc[cc] - mx);
                float lse = mx + logf(s);
#pragma unroll
                for (int cc = 0; cc < CC; cc++) out[row * CC + cc] = acc[cc] - lse;
            }
        }
    } else {
#pragma unroll
        for (int nt = 0; nt < 4; nt++) {
            int col = n0 + nt * 8 + 2 * t;
            float2 bb = *(const float2*)&bias[col];
            int r0 = block_row + m0 + g2;
            int r1 = r0 + 8;
            if (r0 < n) {
                __half2 p = __floats2half2_rn(c[nt][0] + bb.x, c[nt][1] + bb.y);
                OutHh[r0 * 32 + (col >> 1)] = *(unsigned*)&p;
            }
            if (r1 < n) {
                __half2 p = __floats2half2_rn(c[nt][2] + bb.x, c[nt][3] + bb.y);
                OutHh[r1 * 32 + (col >> 1)] = *(unsigned*)&p;
            }
        }
    }
}

// ---------------- launch helpers ----------------
template <typename... Args>
static void launch_pdl(void (*kern)(Args...), dim3 grid, dim3 block,
                       Args... args) {
    cudaLaunchConfig_t cfg = {};
    cfg.gridDim = grid;
    cfg.blockDim = block;
    cfg.stream = 0;
    cudaLaunchAttribute attr[1];
    attr[0].id = cudaLaunchAttributeProgrammaticStreamSerialization;
    attr[0].val.programmaticStreamSerializationAllowed = 1;
    cfg.attrs = attr;
    cfg.numAttrs = 1;
    cudaLaunchKernelEx(&cfg, kern, args...);
}

// ---------------- launch ----------------
extern "C" void kernel_launch(void* const* d_in, const int* in_sizes, int n_in,
                              void* d_out, int out_size) {
    const float* x      = (const float*)d_in[0];
    const void*  ei     = d_in[1];
    const float* enc_w  = (const float*)d_in[3];
    const float* enc_b  = (const float*)d_in[4];
    const float* proc_w = (const float*)d_in[5];
    const float* proc_b = (const float*)d_in[6];
    const float* dec_w  = (const float*)d_in[7];
    const float* dec_b  = (const float*)d_in[8];
    float* out = (float*)d_out;

    unsigned* hhptr = nullptr;
    unsigned* agghptr = nullptr;
    cudaGetSymbolAddress((void**)&hhptr, g_hh);
    cudaGetSymbolAddress((void**)&agghptr, g_aggh);

    const int n = NN;
    const int ggrid = (n + 63) / 64;

    // fork: encoder GEMM runs concurrently with CSR build
    cudaStream_t s2;
    cudaStreamCreateWithFlags(&s2, cudaStreamNonBlocking);
    cudaEvent_t e0, e1;
    cudaEventCreateWithFlags(&e0, cudaEventDisableTiming);
    cudaEventCreateWithFlags(&e1, cudaEventDisableTiming);
    cudaEventRecord(e0, 0);
    cudaStreamWaitEvent(s2, e0, 0);

    // encoder on s2 (fp32 x -> fp16 h); plain launch (different stream)
    gemm_h16_kernel<0><<<ggrid, 256, 0, s2>>>(x, nullptr, nullptr, enc_w, enc_b,
                                              hhptr, nullptr, nullptr, nullptr, n);
    cudaEventRecord(e1, s2);

    // CSR build on capture stream, PDL-chained
    launch_pdl(zerodetect_kernel, dim3((NN + 255) / 256), dim3(256),
               (const unsigned int*)ei);
    launch_pdl(convert_kernel, dim3((EE + 255) / 256), dim3(256), ei);
    launch_pdl(scan_phase1, dim3(SCAN_NBLK), dim3(SCAN_BLK));
    launch_pdl(scan_phase3, dim3(SCAN_NBLK), dim3(SCAN_BLK));
    launch_pdl(scatter_kernel, dim3((EE + 255) / 256), dim3(256), ei);

    // join
    cudaStreamWaitEvent(0, e1, 0);

    // 5 GIN layers (MID), PDL-chained
    for (int it = 0; it < 5; it++) {
        launch_pdl(segmax_kernel, dim3((NN * 32 + 255) / 256), dim3(256));
        launch_pdl(gemm_h16_kernel<1>, dim3(ggrid), dim3(256),
                   (const float*)nullptr, (const unsigned*)hhptr,
                   (const unsigned*)agghptr, proc_w, proc_b, hhptr,
                   (const float*)nullptr, (const float*)nullptr,
                   (float*)nullptr, n);
    }
    // 6th layer fused with decoder + log-softmax (DEC)
    launch_pdl(segmax_kernel, dim3((NN * 32 + 255) / 256), dim3(256));
    launch_pdl(gemm_h16_kernel<2>, dim3(ggrid), dim3(256),
               (const float*)nullptr, (const unsigned*)hhptr,
               (const unsigned*)agghptr, proc_w, proc_b, hhptr,
               dec_w, dec_b, out, n);
}

// round 17
// speedup vs baseline: 1.1381x; 1.0040x over previous
#include <cuda_runtime.h>
#include <cuda_fp16.h>
#include <math.h>
#include <float.h>

#define NN 100000
#define EE 1600000
#define HH 64
#define CC 10
#define SCAN_BLK 1024
#define SCAN_NBLK ((NN + SCAN_BLK - 1) / SCAN_BLK)   // 98

// ---------------- static device scratch ----------------
__device__ int          g_dst[EE];
__device__ int          g_col[EE];
__device__ int          g_deg[NN];
__device__ int          g_rowptr[NN + 1];
__device__ int          g_cursor[NN];
__device__ int          g_partial[SCAN_NBLK];   // block_total+1, 0 = not ready
__device__ unsigned int g_hh[NN * 32];       // fp16x2 node features (the only h)
__device__ unsigned int g_aggh[NN * 32];     // fp16x2 segment-max
__device__ int          g_odd_nonzero;

// PDL: no-ops if the kernel wasn't launched with programmatic serialization.
__device__ __forceinline__ void gdc_launch() {
    asm volatile("griddepcontrol.launch_dependents;" ::: "memory");
}
__device__ __forceinline__ void gdc_wait() {
    asm volatile("griddepcontrol.wait;" ::: "memory");
}

__device__ __forceinline__ uint4 hmax4(uint4 a, uint4 b) {
    uint4 r;
    *(__half2*)&r.x = __hmax2(*(__half2*)&a.x, *(__half2*)&b.x);
    *(__half2*)&r.y = __hmax2(*(__half2*)&a.y, *(__half2*)&b.y);
    *(__half2*)&r.z = __hmax2(*(__half2*)&a.z, *(__half2*)&b.z);
    *(__half2*)&r.w = __hmax2(*(__half2*)&a.w, *(__half2*)&b.w);
    return r;
}
__device__ __forceinline__ uint4 hadd4(uint4 a, uint4 b) {
    uint4 r;
    *(__half2*)&r.x = __hadd2(*(__half2*)&a.x, *(__half2*)&b.x);
    *(__half2*)&r.y = __hadd2(*(__half2*)&a.y, *(__half2*)&b.y);
    *(__half2*)&r.z = __hadd2(*(__half2*)&a.z, *(__half2*)&b.z);
    *(__half2*)&r.w = __hadd2(*(__half2*)&a.w, *(__half2*)&b.w);
    return r;
}

__device__ __forceinline__ void ldm_x4(unsigned& r0, unsigned& r1,
                                       unsigned& r2, unsigned& r3, unsigned addr) {
    asm volatile("ldmatrix.sync.aligned.m8n8.x4.shared.b16 {%0,%1,%2,%3}, [%4];"
                 : "=r"(r0), "=r"(r1), "=r"(r2), "=r"(r3) : "r"(addr));
}
__device__ __forceinline__ void ldm_x2t(unsigned& r0, unsigned& r1, unsigned addr) {
    asm volatile("ldmatrix.sync.aligned.m8n8.x2.trans.shared.b16 {%0,%1}, [%2];"
                 : "=r"(r0), "=r"(r1) : "r"(addr));
}
__device__ __forceinline__ void mma_f16(float c[4], unsigned a0, unsigned a1,
                                        unsigned a2, unsigned a3,
                                        unsigned b0, unsigned b1) {
    asm volatile("mma.sync.aligned.m16n8k16.row.col.f32.f16.f16.f32 "
                 "{%0,%1,%2,%3},{%4,%5,%6,%7},{%8,%9},{%0,%1,%2,%3};"
                 : "+f"(c[0]), "+f"(c[1]), "+f"(c[2]), "+f"(c[3])
                 : "r"(a0), "r"(a1), "r"(a2), "r"(a3), "r"(b0), "r"(b1));
}

// ---------------- setup: zero deg + scan partials + edge dtype detection ----------------
__global__ void zerodetect_kernel(const unsigned int* __restrict__ w) {
    gdc_launch();
    int i = blockIdx.x * blockDim.x + threadIdx.x;
    if (i < NN) g_deg[i] = 0;
    if (i < SCAN_NBLK) g_partial[i] = 0;
    if (i == 0) g_odd_nonzero = 0;
    if (i < 65536) {
        unsigned int v = w[2 * i + 1];
        if (v) atomicOr(&g_odd_nonzero, 1);
    }
}

// 2 edges per thread; dst extraction + degree count.
__global__ void convert_kernel(const void* __restrict__ ei) {
    gdc_launch();
    int i = (blockIdx.x * blockDim.x + threadIdx.x) * 2;
    if (i >= EE) return;
    gdc_wait();                 // flag + deg zeroing from zerodetect
    int d0, d1;
    if (g_odd_nonzero == 0) {
        uint4 v = ((const uint4*)ei)[(EE + i) >> 1];
        d0 = (int)v.x; d1 = (int)v.z;
    } else {
        uint2 v = ((const uint2*)ei)[(EE + i) >> 1];
        d0 = (int)v.x; d1 = (int)v.y;
    }
    *(int2*)(g_dst + i) = make_int2(d0, d1);
    atomicAdd(&g_deg[d0], 1);
    atomicAdd(&g_deg[d1], 1);
}

// ---------------- single-pass exclusive scan (sentinel-publish lookback) ----------------
// 98 blocks, all co-resident (98 < 148 SMs) -> spin on predecessors is safe.
// g_partial[b] carries block_total+1 in one word (0 = not ready; no fence needed).
__global__ void scan_onepass() {
    gdc_launch();
    __shared__ int warp_sums[32];
    __shared__ int warp4[4];
    __shared__ int off_sh;
    int tid = threadIdx.x;
    int bid = blockIdx.x;
    int i = bid * SCAN_BLK + tid;
    int lane = tid & 31, wid = tid >> 5;

    gdc_wait();                 // deg from convert
    int v = (i < NN) ? g_deg[i] : 0;
    int incl = v;
#pragma unroll
    for (int off = 1; off < 32; off <<= 1) {
        int t = __shfl_up_sync(0xffffffffu, incl, off);
        if (lane >= off) incl += t;
    }
    if (lane == 31) warp_sums[wid] = incl;
    __syncthreads();
    if (wid == 0) {
        int ws = warp_sums[lane];
        int wincl = ws;
#pragma unroll
        for (int off = 1; off < 32; off <<= 1) {
            int t = __shfl_up_sync(0xffffffffu, wincl, off);
            if (lane >= off) wincl += t;
        }
        warp_sums[lane] = wincl - ws;       // exclusive warp offsets
        if (lane == 31) {
            // publish ASAP: block_total+1 (data+flag in one word)
            atomicExch(&g_partial[bid], wincl + 1);
            warp4[3] = wincl;               // stash block_total for rowptr[NN]
        }
    }
    __syncthreads();
    int block_total = warp4[3];
    int excl = incl - v + warp_sums[wid];

    // parallel lookback: 128 threads spin/read predecessors
    if (tid < 128) {
        int s = 0;
        if (tid < bid) {                    // bid <= 97 < 128
            int p;
            do { p = ((volatile int*)g_partial)[tid]; } while (p == 0);
            s = p - 1;
        }
#pragma unroll
        for (int off = 16; off > 0; off >>= 1)
            s += __shfl_down_sync(0xffffffffu, s, off);
        if (lane == 0) warp4[tid >> 5] = s;
    }
    __syncthreads();
    if (tid == 0) off_sh = warp4[0] + warp4[1] + warp4[2] + warp4[3 & 3];
    // note warp4[3] was overwritten by lookback warp 3's sum above
    __syncthreads();
    int off = off_sh;
    if (i < NN) {
        int r = excl + off;
        g_rowptr[i] = r;
        g_cursor[i] = r;
    }
    if (bid == SCAN_NBLK - 1 && tid == SCAN_BLK - 1) {
        // off + own block_total: recompute own total from incl of last thread
        g_rowptr[NN] = off + incl;          // last thread's inclusive + warp_off
        // (tid 1023 is in last warp: incl here is warp-local; fix below)
    }
    // robust rowptr[NN]: last block, thread that owns element NN-1 path is messy;
    // instead any thread of last block writes off + block_total_published
    if (bid == SCAN_NBLK - 1 && tid == 0) {
        int p;
        do { p = ((volatile int*)g_partial)[SCAN_NBLK - 1]; } while (p == 0);
        g_rowptr[NN] = off + (p - 1);
    }
}

// 2 edges per thread; scatter src ids into CSR.
__global__ void scatter_kernel(const void* __restrict__ ei) {
    gdc_launch();
    int i = (blockIdx.x * blockDim.x + threadIdx.x) * 2;
    if (i >= EE) return;
    // pre-wait: edge data + dst (transitively complete)
    int s0, s1;
    if (g_odd_nonzero == 0) {
        uint4 v = ((const uint4*)ei)[i >> 1];
        s0 = (int)v.x; s1 = (int)v.z;
    } else {
        uint2 v = ((const uint2*)ei)[i >> 1];
        s0 = (int)v.x; s1 = (int)v.y;
    }
    int2 dd = *(const int2*)(g_dst + i);
    gdc_wait();                 // cursor from scan
    int p0 = atomicAdd(&g_cursor[dd.x], 1);
    g_col[p0] = s0;
    int p1 = atomicAdd(&g_cursor[dd.y], 1);
    g_col[p1] = s1;
}

// ---------------- segment max: 1 warp per node, 4 edges x 8 lanes ----------------
__global__ void segmax_kernel() {
    gdc_launch();
    int gw   = (blockIdx.x * blockDim.x + threadIdx.x) >> 5;
    int lane = threadIdx.x & 31;
    if (gw >= NN) return;
    int beg = g_rowptr[gw], end = g_rowptr[gw + 1];   // pre-wait: rowptr stable
    int grp = lane >> 3;
    int chunk = lane & 7;

    uint4 acc;
    acc.x = acc.y = acc.z = acc.w = 0xFBFFFBFFu;   // (-65504, -65504) half2

    gdc_wait();   // col (first layer: scatter) + hh (later: previous GEMM)

    for (int base = beg; base < end; base += 32) {
        int cnt = min(32, end - base);
        int s = g_col[base + min(lane, cnt - 1)];
#pragma unroll 4
        for (int e4 = 0; e4 < cnt; e4 += 4) {
            int sl = min(e4 + grp, cnt - 1);
            int sv = __shfl_sync(0xffffffffu, s, sl);
            uint4 v = *(const uint4*)(g_hh + sv * 32 + chunk * 4);
            acc = hmax4(acc, v);
        }
    }
#pragma unroll
    for (int off = 8; off <= 16; off <<= 1) {
        uint4 o;
        o.x = __shfl_xor_sync(0xffffffffu, acc.x, off);
        o.y = __shfl_xor_sync(0xffffffffu, acc.y, off);
        o.z = __shfl_xor_sync(0xffffffffu, acc.z, off);
        o.w = __shfl_xor_sync(0xffffffffu, acc.w, off);
        acc = hmax4(acc, o);
    }
    if (beg == end) { acc.x = acc.y = acc.z = acc.w = 0u; }
    if (grp == 0)
        ((uint4*)g_aggh)[gw * 8 + chunk] = acc;
}

// ---------------- fp16 tensor-core GEMM (+fused decoder in DEC mode) ----------------
template <int MODE>
__global__ void __launch_bounds__(256)
gemm_h16_kernel(const float* __restrict__ Ax,
                const unsigned* __restrict__ Hh,
                const unsigned* __restrict__ Aggh,
                const float* __restrict__ W,
                const float* __restrict__ bias,
                unsigned* __restrict__ OutHh,
                const float* __restrict__ dw,
                const float* __restrict__ db,
                float* __restrict__ out, int n) {
    __shared__ __align__(16) __half As[64 * 72];
    __shared__ __align__(16) __half WsH[64 * 72];
    __shared__ __align__(16) __half WsL[64 * 72];
    __shared__ float Hs[(MODE == 2) ? 64 * 66 : 1];
    __shared__ float DWs[(MODE == 2) ? (HH * CC + CC) : 1];

    gdc_launch();
    int tid = threadIdx.x;
    int block_row = blockIdx.x * 64;

    // pre-wait prologue: W/bias/decoder weights are input constants
    for (int i = tid; i < 1024; i += 256) {
        int k = i >> 4, c4 = i & 15;
        float4 v = ((const float4*)W)[i];
        __half h0 = __float2half_rn(v.x), h1 = __float2half_rn(v.y);
        __half h2 = __float2half_rn(v.z), h3 = __float2half_rn(v.w);
        __half l0 = __float2half_rn(v.x - __half2float(h0));
        __half l1 = __float2half_rn(v.y - __half2float(h1));
        __half l2 = __float2half_rn(v.z - __half2float(h2));
        __half l3 = __float2half_rn(v.w - __half2float(h3));
        __half* ph = &WsH[k * 72 + c4 * 4];
        ph[0] = h0; ph[1] = h1; ph[2] = h2; ph[3] = h3;
        __half* pl = &WsL[k * 72 + c4 * 4];
        pl[0] = l0; pl[1] = l1; pl[2] = l2; pl[3] = l3;
    }
    if (MODE == 2) {
        for (int i = tid; i < HH * CC; i += 256) DWs[i] = dw[i];
        if (tid < CC) DWs[HH * CC + tid] = db[tid];
    }

    gdc_wait();   // hh / aggh from previous kernels

    if (MODE == 0) {
        for (int i = tid; i < 1024; i += 256) {
            int m = i >> 4, c = i & 15;
            int row = block_row + m;
            float4 v = make_float4(0.f, 0.f, 0.f, 0.f);
            if (row < n) v = ((const float4*)Ax)[row * 16 + c];
            __half* p = &As[m * 72 + c * 4];
            p[0] = __float2half_rn(v.x); p[1] = __float2half_rn(v.y);
            p[2] = __float2half_rn(v.z); p[3] = __float2half_rn(v.w);
        }
    } else {
        for (int i = tid; i < 512; i += 256) {
            int m = i >> 3, c4 = i & 7;
            int row = block_row + m;
            uint4 v = make_uint4(0u, 0u, 0u, 0u);
            if (row < n) {
                uint4 hv = ((const uint4*)Hh)[row * 8 + c4];
                uint4 av = ((const uint4*)Aggh)[row * 8 + c4];
                v = hadd4(hv, av);
            }
            *(uint4*)&As[m * 72 + c4 * 8] = v;
        }
    }
    __syncthreads();

    int lane = tid & 31, wid = tid >> 5;
    int m0 = (wid & 3) * 16;
    int n0 = (wid >> 2) * 32;

    unsigned sAs = (unsigned)__cvta_generic_to_shared(As);
    unsigned sWH = (unsigned)__cvta_generic_to_shared(WsH);
    unsigned sWL = (unsigned)__cvta_generic_to_shared(WsL);

    int a_row = m0 + ((lane >> 3) & 1) * 8 + (lane & 7);
    int a_k   = ((lane >> 4) & 1) * 8;
    unsigned a_addr = sAs + (a_row * 72 + a_k) * 2;
    int b_k = lane & 15;

    float c[4][4];
#pragma unroll
    for (int i = 0; i < 4; i++)
#pragma unroll
        for (int j = 0; j < 4; j++) c[i][j] = 0.f;

#pragma unroll
    for (int ks = 0; ks < 4; ks++) {
        unsigned a0, a1, a2, a3;
        ldm_x4(a0, a1, a2, a3, a_addr + ks * 32);
        unsigned brow = ((ks * 16 + b_k) * 72 + n0) * 2;
#pragma unroll
        for (int nt = 0; nt < 4; nt++) {
            unsigned bh0, bh1, bl0, bl1;
            ldm_x2t(bh0, bh1, sWH + brow + nt * 16);
            ldm_x2t(bl0, bl1, sWL + brow + nt * 16);
            mma_f16(c[nt], a0, a1, a2, a3, bh0, bh1);
            mma_f16(c[nt], a0, a1, a2, a3, bl0, bl1);
        }
    }

    int g2 = lane >> 2, t = lane & 3;
    if (MODE == 2) {
#pragma unroll
        for (int nt = 0; nt < 4; nt++) {
            int col = n0 + nt * 8 + 2 * t;
            float2 bb = *(const float2*)&bias[col];
            int r0 = m0 + g2;
            Hs[r0 * 66 + col]           = c[nt][0] + bb.x;
            Hs[r0 * 66 + col + 1]       = c[nt][1] + bb.y;
            Hs[(r0 + 8) * 66 + col]     = c[nt][2] + bb.x;
            Hs[(r0 + 8) * 66 + col + 1] = c[nt][3] + bb.y;
        }
        __syncthreads();
        if (tid < 64) {
            int row = block_row + tid;
            if (row < n) {
                float acc[CC];
#pragma unroll
                for (int cc = 0; cc < CC; cc++) acc[cc] = DWs[HH * CC + cc];
#pragma unroll 8
                for (int k = 0; k < HH; k++) {
                    float hv = Hs[tid * 66 + k];
#pragma unroll
                    for (int cc = 0; cc < CC; cc++)
                        acc[cc] += hv * DWs[k * CC + cc];
                }
                float mx = acc[0];
#pragma unroll
                for (int cc = 1; cc < CC; cc++) mx = fmaxf(mx, acc[cc]);
                float s = 0.f;
#pragma unroll
                for (int cc = 0; cc < CC; cc++) s += expf(acc[cc] - mx);
                float lse = mx + logf(s);
#pragma unroll
                for (int cc = 0; cc < CC; cc++) out[row * CC + cc] = acc[cc] - lse;
            }
        }
    } else {
#pragma unroll
        for (int nt = 0; nt < 4; nt++) {
            int col = n0 + nt * 8 + 2 * t;
            float2 bb = *(const float2*)&bias[col];
            int r0 = block_row + m0 + g2;
            int r1 = r0 + 8;
            if (r0 < n) {
                __half2 p = __floats2half2_rn(c[nt][0] + bb.x, c[nt][1] + bb.y);
                OutHh[r0 * 32 + (col >> 1)] = *(unsigned*)&p;
            }
            if (r1 < n) {
                __half2 p = __floats2half2_rn(c[nt][2] + bb.x, c[nt][3] + bb.y);
                OutHh[r1 * 32 + (col >> 1)] = *(unsigned*)&p;
            }
        }
    }
}

// ---------------- launch helpers ----------------
template <typename... Args>
static void launch_pdl(void (*kern)(Args...), dim3 grid, dim3 block,
                       Args... args) {
    cudaLaunchConfig_t cfg = {};
    cfg.gridDim = grid;
    cfg.blockDim = block;
    cfg.stream = 0;
    cudaLaunchAttribute attr[1];
    attr[0].id = cudaLaunchAttributeProgrammaticStreamSerialization;
    attr[0].val.programmaticStreamSerializationAllowed = 1;
    cfg.attrs = attr;
    cfg.numAttrs = 1;
    cudaLaunchKernelEx(&cfg, kern, args...);
}

// ---------------- launch ----------------
extern "C" void kernel_launch(void* const* d_in, const int* in_sizes, int n_in,
                              void* d_out, int out_size) {
    const float* x      = (const float*)d_in[0];
    const void*  ei     = d_in[1];
    const float* enc_w  = (const float*)d_in[3];
    const float* enc_b  = (const float*)d_in[4];
    const float* proc_w = (const float*)d_in[5];
    const float* proc_b = (const float*)d_in[6];
    const float* dec_w  = (const float*)d_in[7];
    const float* dec_b  = (const float*)d_in[8];
    float* out = (float*)d_out;

    unsigned* hhptr = nullptr;
    unsigned* agghptr = nullptr;
    cudaGetSymbolAddress((void**)&hhptr, g_hh);
    cudaGetSymbolAddress((void**)&agghptr, g_aggh);

    const int n = NN;
    const int ggrid = (n + 63) / 64;

    // fork: encoder GEMM runs concurrently with CSR build
    cudaStream_t s2;
    cudaStreamCreateWithFlags(&s2, cudaStreamNonBlocking);
    cudaEvent_t e0, e1;
    cudaEventCreateWithFlags(&e0, cudaEventDisableTiming);
    cudaEventCreateWithFlags(&e1, cudaEventDisableTiming);
    cudaEventRecord(e0, 0);
    cudaStreamWaitEvent(s2, e0, 0);

    // encoder on s2 (fp32 x -> fp16 h); plain launch (different stream)
    gemm_h16_kernel<0><<<ggrid, 256, 0, s2>>>(x, nullptr, nullptr, enc_w, enc_b,
                                              hhptr, nullptr, nullptr, nullptr, n);
    cudaEventRecord(e1, s2);

    // CSR build on capture stream, PDL-chained (4 kernels)
    launch_pdl(zerodetect_kernel, dim3((NN + 255) / 256), dim3(256),
               (const unsigned int*)ei);
    launch_pdl(convert_kernel, dim3((EE / 2 + 255) / 256), dim3(256), ei);
    launch_pdl(scan_onepass, dim3(SCAN_NBLK), dim3(SCAN_BLK));
    launch_pdl(scatter_kernel, dim3((EE / 2 + 255) / 256), dim3(256), ei);

    // join
    cudaStreamWaitEvent(0, e1, 0);

    // 5 GIN layers (MID), PDL-chained
    for (int it = 0; it < 5; it++) {
        launch_pdl(segmax_kernel, dim3((NN * 32 + 255) / 256), dim3(256));
        launch_pdl(gemm_h16_kernel<1>, dim3(ggrid), dim3(256),
                   (const float*)nullptr, (const unsigned*)hhptr,
                   (const unsigned*)agghptr, proc_w, proc_b, hhptr,
                   (const float*)nullptr, (const float*)nullptr,
                   (float*)nullptr, n);
    }
    // 6th layer fused with decoder + log-softmax (DEC)
    launch_pdl(segmax_kernel, dim3((NN * 32 + 255) / 256), dim3(256));
    launch_pdl(gemm_h16_kernel<2>, dim3(ggrid), dim3(256),
               (const float*)nullptr, (const unsigned*)hhptr,
               (const unsigned*)agghptr, proc_w, proc_b, hhptr,
               dec_w, dec_b, out, n);
}